// round 13
// baseline (speedup 1.0000x reference)
#include <cuda_runtime.h>
#include <cuda_fp16.h>
#include <cstdint>

// LorentzConv2d: B=32,H=W=64,C=64,OC=64(+time), 3x3 s1 p1.
// R13: warp mma.sync fp16, 32m x 32n warp tiles, 256-thr CTA (8 warps, 4m x 2n),
// occ 3 -> 24 warps/SM. A via ldmatrix (SW128 smem), B via LDG.128 frags.

// B fragments: [step(tap*4+k)][pair][lane] = {j0.b0, j0.b1, j1.b0, j1.b1}
// n = pair*16 + j*8 + lane/4
__device__ uint4 g_Bf[9 * 4 * 4 * 32];

__device__ __forceinline__ uint32_t pack_h2(float a, float b) {
    __half2 h = __floats2half2_rn(a, b);
    return *(uint32_t*)&h;
}

__global__ void prep_bfrag_kernel(const float* __restrict__ w) {
    int i = blockIdx.x * blockDim.x + threadIdx.x;
    if (i >= 9 * 4 * 4 * 32) return;
    const int lane = i & 31;
    const int pair = (i >> 5) & 3;
    const int kc   = (i >> 7) & 3;
    const int tap  = i >> 9;
    const int k0 = kc * 16 + (lane & 3) * 2;
    uint4 r;
    #pragma unroll
    for (int j = 0; j < 2; ++j) {
        const int n = pair * 16 + j * 8 + (lane >> 2);
        float v0 = (k0 == 0) ? 0.f : w[n * 568 + tap * 63 + k0];
        float v1 = w[n * 568 + tap * 63 + k0 + 1];
        float v2 = w[n * 568 + tap * 63 + k0 + 8];
        float v3 = w[n * 568 + tap * 63 + k0 + 9];
        if (j == 0) { r.x = pack_h2(v0, v1); r.y = pack_h2(v2, v3); }
        else        { r.z = pack_h2(v0, v1); r.w = pack_h2(v2, v3); }
    }
    g_Bf[i] = r;
}

// ---------------- helpers ----------------

#define SWZ(o) ((o) ^ (((o) >> 3) & 0x70))

__device__ __forceinline__ uint32_t s2u(const void* p) {
    uint32_t a;
    asm("{ .reg .u64 t; cvta.to.shared.u64 t, %1; cvt.u32.u64 %0, t; }" : "=r"(a) : "l"(p));
    return a;
}

#define LDSM4(r, addr) \
    asm volatile("ldmatrix.sync.aligned.m8n8.x4.shared.b16 {%0,%1,%2,%3}, [%4];" \
        : "=r"((r)[0]), "=r"((r)[1]), "=r"((r)[2]), "=r"((r)[3]) : "r"(addr))

#define MMA(d, a, b0_, b1_) \
    asm volatile("mma.sync.aligned.m16n8k16.row.col.f32.f16.f16.f32 " \
        "{%0,%1,%2,%3}, {%4,%5,%6,%7}, {%8,%9}, {%0,%1,%2,%3};" \
        : "+f"((d)[0]), "+f"((d)[1]), "+f"((d)[2]), "+f"((d)[3]) \
        : "r"((a)[0]), "r"((a)[1]), "r"((a)[2]), "r"((a)[3]), "r"(b0_), "r"(b1_))

// ---------------- smem layout (bytes) ----------------
// [0..512)      t (128 f)
// [512..768)    bias (64 f)
// [768..1024)   w0 (64 f)
// [1024..2080)  ch0 (264 f)
// [2080..3104)  Ps (2 x 128 f) : per-n-half |y|^2 partials
// [3200..36992) A : 264 slots (4 rows x 66 halo cols) x 128B, SW128
// Os (128x65 f = 33280B) overlays A after mainloop.
#define T_OFF    0u
#define BIAS_OFF 512u
#define W0_OFF   768u
#define CH0_OFF  1024u
#define PS_OFF   2080u
#define A_OFF    3200u
#define SMEM_TOTAL 36992

__global__ __launch_bounds__(256, 3)
void lmma_kernel(const float* __restrict__ x, const float* __restrict__ w,
                 const float* __restrict__ bias, float* __restrict__ out)
{
    extern __shared__ char sm[];
    const uint32_t smb = s2u(sm);
    const int tid  = threadIdx.x;
    const int lane = tid & 31;
    const int wid  = tid >> 5;
    const int wm   = wid & 3;          // m: rows wm*32..+31
    const int wn   = wid >> 2;         // n: cols wn*32..+31
    const int blk  = blockIdx.x;       // 0..1023
    const int b    = blk >> 5;
    const int h0   = (blk & 31) * 2;   // 2 image rows per CTA

    // ---- epilogue params ----
    if (tid < 64) {
        ((float*)(sm + BIAS_OFF))[tid] = bias[tid];
        ((float*)(sm + W0_OFF))[tid]   = w[tid * 568];   // W[:,0]
    }

    // ---- A load: fp32 -> fp16 into swizzled smem; capture channel 0 ----
    {
        const int c4 = tid & 15;
        const int s0 = tid >> 4;       // 0..15
        #pragma unroll 4
        for (int it = 0; it < 17; ++it) {
            const int slot = s0 + it * 16;
            if (slot < 264) {
                const int r = slot / 66, c = slot - r * 66;
                const int hg = h0 - 1 + r, wg = c - 1;
                const uint32_t o = SWZ((uint32_t)slot * 128u + (uint32_t)c4 * 8u);
                float4 v = make_float4(0.f, 0.f, 0.f, 0.f);
                if ((unsigned)hg < 64u && (unsigned)wg < 64u)
                    v = *(const float4*)(x + (size_t)(((b * 64 + hg) * 64 + wg)) * 64 + c4 * 4);
                uint2 hv;
                hv.x = pack_h2(v.x, v.y);
                hv.y = pack_h2(v.z, v.w);
                *(uint2*)(sm + A_OFF + o) = hv;
                if (c4 == 0) ((float*)(sm + CH0_OFF))[slot] = v.x;
            }
        }
    }

    // ---- per-lane invariants ----
    const uint32_t ahalf = (uint32_t)(lane >> 4);
    int Q[2];
    #pragma unroll
    for (int mi = 0; mi < 2; ++mi) {
        const int mloc = wm * 32 + mi * 16 + (lane & 15);
        Q[mi] = (mloc >> 6) * 66 + (mloc & 63);
    }
    const uint4* bp = g_Bf + (size_t)(wn * 2) * 32 + lane;  // + (step*4)*32

    float acc[2][4][4];
    #pragma unroll
    for (int mi = 0; mi < 2; ++mi)
        #pragma unroll
        for (int j = 0; j < 4; ++j)
            #pragma unroll
            for (int q = 0; q < 4; ++q) acc[mi][j][q] = 0.f;

    uint32_t ah[2][2][4];
    uint4    bb[2][2];

    // prefetch B for step 0 before barrier
    bb[0][0] = bp[0];
    bb[0][1] = bp[32];

    __syncthreads();

    // ---- t from staged channel-0 (tid < 128; visible after next barrier) ----
    if (tid < 128) {
        const float* ch0 = (const float*)(sm + CH0_OFF);
        const int base = (tid >> 6) * 66 + (tid & 63);
        float s = 0.f;
        #pragma unroll
        for (int r = 0; r < 3; ++r)
            #pragma unroll
            for (int d = 0; d < 3; ++d) {
                const float m = fmaxf(ch0[base + r * 66 + d], 1.f);
                s += m * m;
            }
        ((float*)(sm + T_OFF))[tid] = sqrtf(s - 8.f);
    }

    // A fragment loader (step = tap*4 + k): both m16 tiles
    auto ld_a = [&](uint32_t (*dst)[4], int s) {
        constexpr int TAPOFF[9] = {0, 1, 2, 66, 67, 68, 132, 133, 134};
        const int tap = s >> 2, k = s & 3;
        #pragma unroll
        for (int mi = 0; mi < 2; ++mi) {
            const uint32_t P = (uint32_t)(Q[mi] + TAPOFF[tap]);
            const uint32_t ao = P * 128u + ((((uint32_t)(k * 2) + ahalf) ^ (P & 7u)) << 4);
            LDSM4(dst[mi], smb + A_OFF + ao);
        }
    };

    ld_a(ah[0], 0);

    // ---- fully unrolled software-pipelined mainloop: 36 steps ----
    #pragma unroll
    for (int s = 0; s < 36; ++s) {
        const int cur = s & 1, nxt = cur ^ 1;
        if (s < 35) {
            ld_a(ah[nxt], s + 1);
            const uint4* p = bp + (size_t)((s + 1) * 4) * 32;
            bb[nxt][0] = p[0];
            bb[nxt][1] = p[32];
        }
        #pragma unroll
        for (int j = 0; j < 4; ++j) {
            const uint4 bq = bb[cur][j >> 1];
            const uint32_t b0 = (j & 1) ? bq.z : bq.x;
            const uint32_t b1 = (j & 1) ? bq.w : bq.y;
            MMA(acc[0][j], ah[cur][0], b0, b1);
            MMA(acc[1][j], ah[cur][1], b0, b1);
        }
    }

    // ---- epilogue ----
    __syncthreads();   // all LDSM done before Os overlays A; t visible

    const float* ts  = (const float*)(sm + T_OFF);
    const float* bs  = (const float*)(sm + BIAS_OFF);
    const float* w0s = (const float*)(sm + W0_OFF);
    float* Ps = (float*)(sm + PS_OFF);
    float* Os = (float*)(sm + A_OFF);

    #pragma unroll
    for (int mi = 0; mi < 2; ++mi) {
        const int m0 = wm * 32 + mi * 16 + (lane >> 2);
        const float t0 = ts[m0], t8 = ts[m0 + 8];
        float s0 = 0.f, s8 = 0.f;
        #pragma unroll
        for (int j = 0; j < 4; ++j) {
            const int n0 = wn * 32 + j * 8 + (lane & 3) * 2;
            const float b0v = bs[n0],  b1v = bs[n0 + 1];
            const float w0v = w0s[n0], w1v = w0s[n0 + 1];
            const float v0 = acc[mi][j][0] + b0v + t0 * w0v;
            const float v1 = acc[mi][j][1] + b1v + t0 * w1v;
            const float v2 = acc[mi][j][2] + b0v + t8 * w0v;
            const float v3 = acc[mi][j][3] + b1v + t8 * w1v;
            Os[m0 * 65 + 1 + n0]       = v0;
            Os[m0 * 65 + 2 + n0]       = v1;
            Os[(m0 + 8) * 65 + 1 + n0] = v2;
            Os[(m0 + 8) * 65 + 2 + n0] = v3;
            s0 += v0 * v0 + v1 * v1;
            s8 += v2 * v2 + v3 * v3;
        }
        s0 += __shfl_xor_sync(0xffffffffu, s0, 1);
        s0 += __shfl_xor_sync(0xffffffffu, s0, 2);
        s8 += __shfl_xor_sync(0xffffffffu, s8, 1);
        s8 += __shfl_xor_sync(0xffffffffu, s8, 2);
        if ((lane & 3) == 0) {
            Ps[wn * 128 + m0]     = s0;
            Ps[wn * 128 + m0 + 8] = s8;
        }
    }
    __syncthreads();

    if (tid < 128) {
        const float s = Ps[tid] + Ps[128 + tid];
        Os[tid * 65] = sqrtf(s + 1.f);
    }
    __syncthreads();

    // ---- coalesced float4 writeback (2080 vecs, 256 threads) ----
    float4* og = (float4*)(out + (size_t)blk * 128 * 65);
    const float4* ov = (const float4*)Os;
    #pragma unroll
    for (int it = 0; it < 8; ++it) og[tid + it * 256] = ov[tid + it * 256];
    if (tid < 32) og[tid + 8 * 256] = ov[tid + 8 * 256];
}

// ---------------- launch ----------------

extern "C" void kernel_launch(void* const* d_in, const int* in_sizes, int n_in,
                              void* d_out, int out_size) {
    const float* x    = (const float*)d_in[0];
    const float* w    = (const float*)d_in[1];
    const float* bias = (const float*)d_in[2];
    float* out = (float*)d_out;

    cudaFuncSetAttribute(lmma_kernel, cudaFuncAttributeMaxDynamicSharedMemorySize, SMEM_TOTAL);

    prep_bfrag_kernel<<<(9 * 4 * 4 * 32 + 255) / 256, 256>>>(w);
    lmma_kernel<<<1024, 256, SMEM_TOTAL>>>(x, w, bias, out);
}

// round 14
// speedup vs baseline: 1.2393x; 1.2393x over previous
#include <cuda_runtime.h>
#include <cuda_fp16.h>
#include <cstdint>

// LorentzConv2d: B=32,H=W=64,C=64,OC=64(+time), 3x3 s1 p1.
// Warp mma.sync fp16 (fp32 accum), 32m x 64n warp tiles, 128-thr CTA, occ 4.
// A via ldmatrix (SW128 smem), B via LDG.128 pre-baked frags (R7 mainloop).
// R14 = R9 (best measured config: 36.5us). R10-R13 probed CTA size, warp
// tile, epilogue style, scheduling -- all regressed; this is the optimum.

// B fragments: [step(tap*4+k)][pair][lane] = {j0.b0, j0.b1, j1.b0, j1.b1}
// n = pair*16 + j*8 + lane/4
__device__ uint4 g_Bf[9 * 4 * 4 * 32];

__device__ __forceinline__ uint32_t pack_h2(float a, float b) {
    __half2 h = __floats2half2_rn(a, b);
    return *(uint32_t*)&h;
}

__global__ void prep_bfrag_kernel(const float* __restrict__ w) {
    int i = blockIdx.x * blockDim.x + threadIdx.x;
    if (i >= 9 * 4 * 4 * 32) return;
    const int lane = i & 31;
    const int pair = (i >> 5) & 3;
    const int kc   = (i >> 7) & 3;
    const int tap  = i >> 9;
    const int k0 = kc * 16 + (lane & 3) * 2;
    uint4 r;
    #pragma unroll
    for (int j = 0; j < 2; ++j) {
        const int n = pair * 16 + j * 8 + (lane >> 2);
        float v0 = (k0 == 0) ? 0.f : w[n * 568 + tap * 63 + k0];
        float v1 = w[n * 568 + tap * 63 + k0 + 1];
        float v2 = w[n * 568 + tap * 63 + k0 + 8];
        float v3 = w[n * 568 + tap * 63 + k0 + 9];
        if (j == 0) { r.x = pack_h2(v0, v1); r.y = pack_h2(v2, v3); }
        else        { r.z = pack_h2(v0, v1); r.w = pack_h2(v2, v3); }
    }
    g_Bf[i] = r;
}

// ---------------- helpers ----------------

#define SWZ(o) ((o) ^ (((o) >> 3) & 0x70))

__device__ __forceinline__ uint32_t s2u(const void* p) {
    uint32_t a;
    asm("{ .reg .u64 t; cvta.to.shared.u64 t, %1; cvt.u32.u64 %0, t; }" : "=r"(a) : "l"(p));
    return a;
}

#define LDSM4(r, addr) \
    asm volatile("ldmatrix.sync.aligned.m8n8.x4.shared.b16 {%0,%1,%2,%3}, [%4];" \
        : "=r"((r)[0]), "=r"((r)[1]), "=r"((r)[2]), "=r"((r)[3]) : "r"(addr))

#define MMA(d, a, b0_, b1_) \
    asm volatile("mma.sync.aligned.m16n8k16.row.col.f32.f16.f16.f32 " \
        "{%0,%1,%2,%3}, {%4,%5,%6,%7}, {%8,%9}, {%0,%1,%2,%3};" \
        : "+f"((d)[0]), "+f"((d)[1]), "+f"((d)[2]), "+f"((d)[3]) \
        : "r"((a)[0]), "r"((a)[1]), "r"((a)[2]), "r"((a)[3]), "r"(b0_), "r"(b1_))

// ---------------- smem layout (bytes) ----------------
// [0..512)      t (128 f)
// [512..768)    bias (64 f)
// [768..1024)   w0 (64 f)
// [1024..2080)  ch0 (264 f) : fp32 channel-0 per halo slot
// [3072..36864) A : 264 slots (4 rows x 66 halo cols) x 128B (64ch fp16), SW128
// Os (128x65 f = 33280B) overlays A after mainloop.
#define T_OFF    0u
#define BIAS_OFF 512u
#define W0_OFF   768u
#define CH0_OFF  1024u
#define A_OFF    3072u
#define SMEM_TOTAL 36864

// per-tap slot deltas: (r*66 + dw)
__device__ __constant__ int c_tapoff[9] = {0, 1, 2, 66, 67, 68, 132, 133, 134};

__global__ __launch_bounds__(128, 4)
void lmma_kernel(const float* __restrict__ x, const float* __restrict__ w,
                 const float* __restrict__ bias, float* __restrict__ out)
{
    extern __shared__ char sm[];
    const uint32_t smb = s2u(sm);
    const int tid  = threadIdx.x;
    const int lane = tid & 31;
    const int wid  = tid >> 5;         // warp = m-slice: rows wid*32..+31, all 64 n
    const int blk  = blockIdx.x;       // 0..1023
    const int b    = blk >> 5;
    const int h0   = (blk & 31) * 2;   // 2 image rows per CTA

    // ---- epilogue params ----
    if (tid < 64) {
        ((float*)(sm + BIAS_OFF))[tid] = bias[tid];
        ((float*)(sm + W0_OFF))[tid]   = w[tid * 568];   // W[:,0]
    }

    // ---- A load: fp32 -> fp16 into swizzled smem; capture channel 0 ----
    {
        const int c4 = tid & 15;
        for (int slot = tid >> 4; slot < 264; slot += 8) {
            const int r = slot / 66, c = slot - r * 66;
            const int hg = h0 - 1 + r, wg = c - 1;
            const uint32_t o = SWZ((uint32_t)slot * 128u + (uint32_t)c4 * 8u);
            float4 v = make_float4(0.f, 0.f, 0.f, 0.f);
            if ((unsigned)hg < 64u && (unsigned)wg < 64u)
                v = *(const float4*)(x + (size_t)(((b * 64 + hg) * 64 + wg)) * 64 + c4 * 4);
            uint2 hv;
            hv.x = pack_h2(v.x, v.y);
            hv.y = pack_h2(v.z, v.w);
            *(uint2*)(sm + A_OFF + o) = hv;
            if (c4 == 0) ((float*)(sm + CH0_OFF))[slot] = v.x;   // channel 0, fp32
        }
    }

    // ---- per-lane invariants ----
    const uint32_t ahalf = (uint32_t)(lane >> 4);
    int Q[2];
    #pragma unroll
    for (int mi = 0; mi < 2; ++mi) {
        const int mloc = wid * 32 + mi * 16 + (lane & 15);
        Q[mi] = (mloc >> 6) * 66 + (mloc & 63);
    }
    const uint4* bp = g_Bf + lane;     // + (step*4 + pair)*32

    float acc[2][8][4];
    #pragma unroll
    for (int mi = 0; mi < 2; ++mi)
        #pragma unroll
        for (int j = 0; j < 8; ++j)
            #pragma unroll
            for (int q = 0; q < 4; ++q) acc[mi][j][q] = 0.f;

    uint32_t ah[2][2][4];
    uint4    bb[2][4];

    // prefetch B for step 0 before barrier (gmem, independent of smem A)
    #pragma unroll
    for (int p = 0; p < 4; ++p) bb[0][p] = bp[p * 32];

    __syncthreads();

    // ---- t from staged channel-0 (fp32 exact, conflict-free LDS) ----
    {
        const float* ch0 = (const float*)(sm + CH0_OFF);
        const int base = (tid >> 6) * 66 + (tid & 63);
        float s = 0.f;
        #pragma unroll
        for (int r = 0; r < 3; ++r)
            #pragma unroll
            for (int d = 0; d < 3; ++d) {
                const float m = fmaxf(ch0[base + r * 66 + d], 1.f);
                s += m * m;
            }
        ((float*)(sm + T_OFF))[tid] = sqrtf(s - 8.f);
        // visible after the pre-epilogue __syncthreads()
    }

    // A fragment loader (step = tap*4 + k): both m16 tiles
    auto ld_a = [&](uint32_t (*dst)[4], int s) {
        const int tap = s >> 2, k = s & 3;
        #pragma unroll
        for (int mi = 0; mi < 2; ++mi) {
            const uint32_t P = (uint32_t)(Q[mi] + c_tapoff[tap]);
            const uint32_t ao = P * 128u + ((((uint32_t)(k * 2) + ahalf) ^ (P & 7u)) << 4);
            LDSM4(dst[mi], smb + A_OFF + ao);
        }
    };

    ld_a(ah[0], 0);

    // ---- fully unrolled software-pipelined mainloop: 36 steps ----
    #pragma unroll
    for (int s = 0; s < 36; ++s) {
        const int cur = s & 1, nxt = cur ^ 1;
        if (s < 35) {
            ld_a(ah[nxt], s + 1);
            const uint4* p = bp + (size_t)((s + 1) * 4) * 32;
            #pragma unroll
            for (int q = 0; q < 4; ++q) bb[nxt][q] = p[q * 32];
        }
        #pragma unroll
        for (int j = 0; j < 8; ++j) {
            const uint4 bq = bb[cur][j >> 1];
            const uint32_t b0 = (j & 1) ? bq.z : bq.x;
            const uint32_t b1 = (j & 1) ? bq.w : bq.y;
            MMA(acc[0][j], ah[cur][0], b0, b1);
            MMA(acc[1][j], ah[cur][1], b0, b1);
        }
    }

    // ---- epilogue ----
    __syncthreads();   // all LDSM done before Os overlays A; t visible

    const float* ts  = (const float*)(sm + T_OFF);
    const float* bs  = (const float*)(sm + BIAS_OFF);
    const float* w0s = (const float*)(sm + W0_OFF);
    float* Os = (float*)(sm + A_OFF);

    #pragma unroll
    for (int mi = 0; mi < 2; ++mi) {
        const int m0 = wid * 32 + mi * 16 + (lane >> 2);
        const float t0 = ts[m0], t8 = ts[m0 + 8];
        float s0 = 0.f, s8 = 0.f;
        #pragma unroll
        for (int j = 0; j < 8; ++j) {
            const int n0 = j * 8 + (lane & 3) * 2;
            const float b0v = bs[n0],  b1v = bs[n0 + 1];
            const float w0v = w0s[n0], w1v = w0s[n0 + 1];
            const float v0 = acc[mi][j][0] + b0v + t0 * w0v;
            const float v1 = acc[mi][j][1] + b1v + t0 * w1v;
            const float v2 = acc[mi][j][2] + b0v + t8 * w0v;
            const float v3 = acc[mi][j][3] + b1v + t8 * w1v;
            Os[m0 * 65 + 1 + n0]       = v0;
            Os[m0 * 65 + 2 + n0]       = v1;
            Os[(m0 + 8) * 65 + 1 + n0] = v2;
            Os[(m0 + 8) * 65 + 2 + n0] = v3;
            s0 += v0 * v0 + v1 * v1;
            s8 += v2 * v2 + v3 * v3;
        }
        s0 += __shfl_xor_sync(0xffffffffu, s0, 1);
        s0 += __shfl_xor_sync(0xffffffffu, s0, 2);
        s8 += __shfl_xor_sync(0xffffffffu, s8, 1);
        s8 += __shfl_xor_sync(0xffffffffu, s8, 2);
        if ((lane & 3) == 0) {
            Os[m0 * 65]       = sqrtf(s0 + 1.f);
            Os[(m0 + 8) * 65] = sqrtf(s8 + 1.f);
        }
    }
    __syncthreads();

    float4* og = (float4*)(out + (size_t)blk * 128 * 65);
    const float4* ov = (const float4*)Os;
    #pragma unroll 4
    for (int i = tid; i < 128 * 65 / 4; i += 128) og[i] = ov[i];
}

// ---------------- launch ----------------

extern "C" void kernel_launch(void* const* d_in, const int* in_sizes, int n_in,
                              void* d_out, int out_size) {
    const float* x    = (const float*)d_in[0];
    const float* w    = (const float*)d_in[1];
    const float* bias = (const float*)d_in[2];
    float* out = (float*)d_out;

    cudaFuncSetAttribute(lmma_kernel, cudaFuncAttributeMaxDynamicSharedMemorySize, SMEM_TOTAL);

    prep_bfrag_kernel<<<(9 * 4 * 4 * 32 + 255) / 256, 256>>>(w);
    lmma_kernel<<<1024, 128, SMEM_TOTAL>>>(x, w, bias, out);
}